// round 6
// baseline (speedup 1.0000x reference)
#include <cuda_runtime.h>
#include <cuda_bf16.h>
#include <math.h>

#define BB 32
#define HH 64
#define WW 64

typedef unsigned long long ull;

#define FFMA2(d, a, b, c) \
    asm("fma.rn.f32x2 %0, %1, %2, %3;" : "=l"(d) : "l"(a), "l"(b), "l"(c))
#define PACK2(dst, lo, hi) \
    asm("mov.b64 %0, {%1, %2};" : "=l"(dst) : "f"(lo), "f"(hi))
#define UNPACK2(lo, hi, src) \
    asm("mov.b64 {%0, %1}, %2;" : "=f"(lo), "=f"(hi) : "l"(src))

// u scratch: [pix][(d*8+c)*8 + n]   (256 MB)
__device__ float g_u[(size_t)BB * HH * WW * 512];
// v scratch: [pix][n*8+d]           (32 MB)
__device__ float g_v[(size_t)BB * HH * WW * 64];

// ---------------------------------------------------------------------------
// K1a: ConvTrans (grouped 3x3) -> u in gmem.
// Tile 4 rows x 8 cols. blockDim (64, 8) = 512 thr: tx = c*8+dh, ty = col.
// Each thread: 4 rows x 8 n (packed f32x2). 2 blocks/SM.
// s_in transposed to [pix][c*8+din] so iv loads broadcast within warp.
// ---------------------------------------------------------------------------
#define K1A_SMEM_FLOATS (3840 + 8192)
#define K1A_SMEM_BYTES  (K1A_SMEM_FLOATS * 4)

__global__ __launch_bounds__(512, 2)
void convcaps_conv(const float* __restrict__ x,    // [B,H,W,64] ch = d*8+c
                   const float* __restrict__ CTW,  // [9][8 din][512] c*64+dh*8+n
                   const float* __restrict__ CTB)  // [512]
{
    extern __shared__ float sm[];
    float* s_in = sm;            // 6 rows x 10 cols x 64 (transposed ch)
    float* s_w  = sm + 3840;     // 2 x 4096 double buffer

    const int tx = threadIdx.x;  // 0..63
    const int ty = threadIdx.y;  // 0..7 (column)
    const int tid = ty * 64 + tx;

    const int b  = blockIdx.z;
    const int h0 = blockIdx.y * 4;
    const int w0 = blockIdx.x * 8;

    // ---- load + transpose input tile with halo: 6x10 pixels x 64 ch ----
    for (int i = tid; i < 60 * 16; i += 512) {
        int q = i & 15;
        int p = i >> 4;              // 0..59
        int row = p / 10, col = p % 10;
        int gh = h0 + row - 1, gw = w0 + col - 1;
        float4 val = make_float4(0.f, 0.f, 0.f, 0.f);
        if ((unsigned)gh < (unsigned)HH && (unsigned)gw < (unsigned)WW)
            val = *(const float4*)(x + (((size_t)(b * HH + gh) * WW + gw) * 64) + q * 4);
        float* base = s_in + p * 64;
        int ch = q * 4;
        // transpose: ch = d*8+c  ->  c*8+d
        base[((ch    ) & 7) * 8 + ((ch    ) >> 3)] = val.x;
        base[((ch + 1) & 7) * 8 + ((ch + 1) >> 3)] = val.y;
        base[((ch + 2) & 7) * 8 + ((ch + 2) >> 3)] = val.z;
        base[((ch + 3) & 7) * 8 + ((ch + 3) >> 3)] = val.w;
    }

    const int c  = tx >> 3;
    const int dh = tx & 7;

    ull acc2[4][4];
    {
        const float4* bp = (const float4*)(CTB + c * 64 + dh * 8);
        float4 b0 = __ldg(bp), b1 = __ldg(bp + 1);
        ull bias2[4];
        PACK2(bias2[0], b0.x, b0.y);
        PACK2(bias2[1], b0.z, b0.w);
        PACK2(bias2[2], b1.x, b1.y);
        PACK2(bias2[3], b1.z, b1.w);
        #pragma unroll
        for (int p = 0; p < 4; p++)
            #pragma unroll
            for (int j = 0; j < 4; j++)
                acc2[p][j] = bias2[j];
    }

    // stage tap-0 weights: 4096 floats = 1024 float4 (2 per thread)
    ((float4*)s_w)[tid]       = __ldg((const float4*)CTW + tid);
    ((float4*)s_w)[tid + 512] = __ldg((const float4*)CTW + tid + 512);
    __syncthreads();

    for (int tap = 0; tap < 9; tap++) {
        float4 wn0, wn1;
        if (tap < 8) {
            wn0 = __ldg((const float4*)CTW + (tap + 1) * 1024 + tid);
            wn1 = __ldg((const float4*)CTW + (tap + 1) * 1024 + tid + 512);
        }

        const float* wslab = s_w + (tap & 1) * 4096;
        const int ky = tap / 3, kx = tap % 3;
        const float* inb0 = s_in + (ky * 10 + ty + kx) * 64 + c * 8;

        #pragma unroll
        for (int din = 0; din < 8; din++) {
            const ulonglong2* wp = (const ulonglong2*)(wslab + din * 512 + c * 64 + dh * 8);
            ulonglong2 wA = wp[0], wB = wp[1];
            const float* inb = inb0 + din;
            #pragma unroll
            for (int r = 0; r < 4; r++) {
                float iv = inb[r * 640];
                ull iv2; PACK2(iv2, iv, iv);
                FFMA2(acc2[r][0], iv2, wA.x, acc2[r][0]);
                FFMA2(acc2[r][1], iv2, wA.y, acc2[r][1]);
                FFMA2(acc2[r][2], iv2, wB.x, acc2[r][2]);
                FFMA2(acc2[r][3], iv2, wB.y, acc2[r][3]);
            }
        }

        if (tap < 8) {
            float* alt = s_w + ((tap + 1) & 1) * 4096;
            ((float4*)alt)[tid]       = wn0;
            ((float4*)alt)[tid + 512] = wn1;
        }
        __syncthreads();
    }

    // ---- write u: g_u[pix][(dh*8+c)*8 + n] ----
    #pragma unroll
    for (int r = 0; r < 4; r++) {
        float v[8];
        #pragma unroll
        for (int j = 0; j < 4; j++)
            UNPACK2(v[2 * j], v[2 * j + 1], acc2[r][j]);
        size_t pix = ((size_t)(b * HH + h0 + r) * WW + w0 + ty);
        float* up = g_u + pix * 512 + (dh * 8 + c) * 8;
        *(float4*)(up)     = make_float4(v[0], v[1], v[2], v[3]);
        *(float4*)(up + 4) = make_float4(v[4], v[5], v[6], v[7]);
    }
}

// ---------------------------------------------------------------------------
// K1b: attention (logits + softmax over o + weighted sum) -> v in gmem.
// 256 threads: 32 pixels/block, thread = (pixel, n). u row (64 fl) in regs.
// ---------------------------------------------------------------------------
__global__ __launch_bounds__(256, 2)
void convcaps_attn(const float* __restrict__ AW)   // [64 dc][64] dc*64 + n*8 + o
{
    __shared__ float sA[4096];
    const int tid = threadIdx.x;

    #pragma unroll
    for (int j = 0; j < 4; j++)
        ((float4*)sA)[tid + j * 256] = __ldg((const float4*)AW + tid + j * 256);

    const size_t pix = (size_t)blockIdx.x * 32 + (tid >> 3);
    const int n = tid & 7;
    const float* up = g_u + pix * 512 + n;

    // load u[d][c] for this n into regs
    float uv[64];
    #pragma unroll
    for (int dc = 0; dc < 64; dc++)
        uv[dc] = __ldg(up + dc * 8);

    __syncthreads();

    // logits over o
    float lg[8] = {0.f, 0.f, 0.f, 0.f, 0.f, 0.f, 0.f, 0.f};
    #pragma unroll 8
    for (int dc = 0; dc < 64; dc++) {
        const float4* ap = (const float4*)(sA + dc * 64 + n * 8);
        float4 a0 = ap[0], a1 = ap[1];
        float u0 = uv[dc];
        lg[0] = fmaf(u0, a0.x, lg[0]);
        lg[1] = fmaf(u0, a0.y, lg[1]);
        lg[2] = fmaf(u0, a0.z, lg[2]);
        lg[3] = fmaf(u0, a0.w, lg[3]);
        lg[4] = fmaf(u0, a1.x, lg[4]);
        lg[5] = fmaf(u0, a1.y, lg[5]);
        lg[6] = fmaf(u0, a1.z, lg[6]);
        lg[7] = fmaf(u0, a1.w, lg[7]);
    }

    // softmax over o
    float m = lg[0];
    #pragma unroll
    for (int o = 1; o < 8; o++) m = fmaxf(m, lg[o]);
    float att[8];
    float s = 0.f;
    #pragma unroll
    for (int o = 0; o < 8; o++) { att[o] = __expf(lg[o] - m); s += att[o]; }
    float inv = 1.f / s;
    #pragma unroll
    for (int o = 0; o < 8; o++) att[o] *= inv;

    // v[d] = sum_o u[d][o] * att[o]
    float v[8];
    #pragma unroll
    for (int d = 0; d < 8; d++) {
        float acc = 0.f;
        #pragma unroll
        for (int o = 0; o < 8; o++)
            acc = fmaf(uv[d * 8 + o], att[o], acc);
        v[d] = acc;
    }

    float* vp = g_v + pix * 64 + n * 8;
    *(float4*)(vp)     = make_float4(v[0], v[1], v[2], v[3]);
    *(float4*)(vp + 4) = make_float4(v[4], v[5], v[6], v[7]);
}

// ---------------------------------------------------------------------------
// K2: FeaExt (grouped 3x3) + ReLU + CapsAct (grouped 1x1) -> out
// Tile 4 rows x 32 cols. 256 thr: (pc = tid&31, n = tid>>5), 4 rows/thread.
// s_v stride 66 (bank decorrelated). 3 blocks/SM.
// ---------------------------------------------------------------------------
#define SVP 66
#define K2_SMEM_FLOATS (204 * SVP + 4608 + 512 + 64 + 64)
#define K2_SMEM_BYTES  (K2_SMEM_FLOATS * 4)

__global__ __launch_bounds__(256, 3)
void convcaps_k2(const float* __restrict__ FW,  // [9][8 d][64] n*8+e
                 const float* __restrict__ FB,  // [64]
                 const float* __restrict__ CW,  // [8 e][64]    n*8+f
                 const float* __restrict__ CB,  // [64]
                 float* __restrict__ out)       // [B,H,W,64] ch = f*8+n
{
    extern __shared__ float sm2[];
    float* s_v  = sm2;                    // 204 * 66
    float* s_fw = s_v + 204 * SVP;        // 4608
    float* s_cw = s_fw + 4608;            // 512
    float* s_fb = s_cw + 512;             // 64
    float* s_cb = s_fb + 64;              // 64

    const int tid = threadIdx.x;          // 0..255
    const int pc  = tid & 31;
    const int n   = tid >> 5;

    const int b  = blockIdx.z;
    const int h0 = blockIdx.y * 4;
    const int w0 = blockIdx.x * 32;

    // ---- v tile with halo: 6 rows x 34 cols ----
    for (int i = tid; i < 204 * 32; i += 256) {
        int hp = i >> 5;
        int q  = i & 31;
        int row  = hp / 34;
        int colh = hp % 34;
        int gh = h0 + row - 1;
        int gw = w0 + colh - 1;
        float2 val = make_float2(0.f, 0.f);
        if ((unsigned)gh < (unsigned)HH && (unsigned)gw < (unsigned)WW)
            val = *(const float2*)(g_v + (((size_t)(b * HH + gh) * WW + gw) * 64) + q * 2);
        *(float2*)(s_v + hp * SVP + q * 2) = val;
    }
    for (int i = tid; i < 1152; i += 256) ((float4*)s_fw)[i] = __ldg((const float4*)FW + i);
    if (tid < 128) ((float4*)s_cw)[tid] = __ldg((const float4*)CW + tid);
    if (tid < 64) { s_fb[tid] = __ldg(FB + tid); s_cb[tid] = __ldg(CB + tid); }
    __syncthreads();

    // FeaExt accumulators: 4 rows x 8 e packed
    ull h1[4][4];
    {
        const ulonglong2* fb = (const ulonglong2*)(s_fb + n * 8);
        ulonglong2 f0 = fb[0], f1 = fb[1];
        #pragma unroll
        for (int pr = 0; pr < 4; pr++) {
            h1[pr][0] = f0.x; h1[pr][1] = f0.y;
            h1[pr][2] = f1.x; h1[pr][3] = f1.y;
        }
    }

    #pragma unroll
    for (int tap = 0; tap < 9; tap++) {
        const int ky = tap / 3, kx = tap % 3;
        const float* vbase = s_v + (ky * 34 + pc + kx) * SVP + n * 8;
        #pragma unroll
        for (int d = 0; d < 8; d++) {
            const ulonglong2* wp = (const ulonglong2*)(s_fw + (tap * 8 + d) * 64 + n * 8);
            ulonglong2 wA = wp[0], wB = wp[1];
            const float* vp = vbase + d;
            #pragma unroll
            for (int pr = 0; pr < 4; pr++) {
                float iv = vp[pr * (34 * SVP)];
                ull iv2; PACK2(iv2, iv, iv);
                FFMA2(h1[pr][0], iv2, wA.x, h1[pr][0]);
                FFMA2(h1[pr][1], iv2, wA.y, h1[pr][1]);
                FFMA2(h1[pr][2], iv2, wB.x, h1[pr][2]);
                FFMA2(h1[pr][3], iv2, wB.y, h1[pr][3]);
            }
        }
    }

    const ulonglong2* cbp = (const ulonglong2*)(s_cb + n * 8);
    ulonglong2 cb0 = cbp[0], cb1 = cbp[1];

    #pragma unroll
    for (int pr = 0; pr < 4; pr++) {
        float e[8];
        #pragma unroll
        for (int j = 0; j < 4; j++)
            UNPACK2(e[2 * j], e[2 * j + 1], h1[pr][j]);
        #pragma unroll
        for (int k = 0; k < 8; k++) e[k] = fmaxf(e[k], 0.f);

        ull h2[4] = {cb0.x, cb0.y, cb1.x, cb1.y};
        #pragma unroll
        for (int k = 0; k < 8; k++) {
            ull he2; PACK2(he2, e[k], e[k]);
            const ulonglong2* cwp = (const ulonglong2*)(s_cw + k * 64 + n * 8);
            ulonglong2 cA = cwp[0], cB = cwp[1];
            FFMA2(h2[0], he2, cA.x, h2[0]);
            FFMA2(h2[1], he2, cA.y, h2[1]);
            FFMA2(h2[2], he2, cB.x, h2[2]);
            FFMA2(h2[3], he2, cB.y, h2[3]);
        }

        float r[8];
        #pragma unroll
        for (int j = 0; j < 4; j++)
            UNPACK2(r[2 * j], r[2 * j + 1], h2[j]);

        const int gh = h0 + pr, gw = w0 + pc;
        float* ob = out + ((size_t)(b * HH + gh) * WW + gw) * 64;
        #pragma unroll
        for (int f = 0; f < 8; f++)
            ob[f * 8 + n] = r[f];
    }
}

// ---------------------------------------------------------------------------
extern "C" void kernel_launch(void* const* d_in, const int* in_sizes, int n_in,
                              void* d_out, int out_size) {
    (void)in_sizes; (void)n_in; (void)out_size;
    const float* x   = (const float*)d_in[0];
    const float* AW  = (const float*)d_in[1];
    const float* CTW = (const float*)d_in[2];
    const float* CTB = (const float*)d_in[3];
    const float* FW  = (const float*)d_in[4];
    const float* FB  = (const float*)d_in[5];
    const float* CW  = (const float*)d_in[6];
    const float* CB  = (const float*)d_in[7];

    cudaFuncSetAttribute(convcaps_conv,
                         cudaFuncAttributeMaxDynamicSharedMemorySize, K1A_SMEM_BYTES);
    cudaFuncSetAttribute(convcaps_k2,
                         cudaFuncAttributeMaxDynamicSharedMemorySize, K2_SMEM_BYTES);

    dim3 gridA(WW / 8, HH / 4, BB);
    convcaps_conv<<<gridA, dim3(64, 8), K1A_SMEM_BYTES>>>(x, CTW, CTB);

    convcaps_attn<<<(BB * HH * WW) / 32, 256>>>(AW);

    dim3 grid2(WW / 32, HH / 4, BB);
    convcaps_k2<<<grid2, 256, K2_SMEM_BYTES>>>(FW, FB, CW, CB, (float*)d_out);
}

// round 8
// speedup vs baseline: 1.3351x; 1.3351x over previous
#include <cuda_runtime.h>
#include <cuda_bf16.h>
#include <math.h>

#define BB 32
#define HH 64
#define WW 64

typedef unsigned long long ull;

#define FFMA2(d, a, b, c) \
    asm("fma.rn.f32x2 %0, %1, %2, %3;" : "=l"(d) : "l"(a), "l"(b), "l"(c))
#define PACK2(dst, lo, hi) \
    asm("mov.b64 %0, {%1, %2};" : "=l"(dst) : "f"(lo), "f"(hi))
#define UNPACK2(lo, hi, src) \
    asm("mov.b64 {%0, %1}, %2;" : "=f"(lo), "=f"(hi) : "l"(src))

// v scratch: [pix][n*8+d]  (32 MB)
__device__ float g_v[(size_t)BB * HH * WW * 64];

// ---------------------------------------------------------------------------
// K1: ConvTrans + attention (fused, u stays in smem).
// Tile: 1 row x 32 cols. 256 threads.
//  Phase A (conv): warp = c (8 warps), lane = pixel column.
//    Thread accumulates all 64 (dh,n) outputs, packed as 32 f32x2.
//    Weights broadcast within warp (slab in smem, double-buffered);
//    iv per-lane, s_in stride 65 -> conflict-free.
//  Phase B (attention): thread = (px, n). u row in regs, A in smem.
// smem: union{ s_in(6656, 16B-aligned pad) + s_w(2*4096) | s_u(32*520=16640) }
//       + sA 4096
// ---------------------------------------------------------------------------
#define K1_SMEM_FLOATS (16640 + 4096)
#define K1_SMEM_BYTES  (K1_SMEM_FLOATS * 4)
#define SUP 520
#define SW_OFF 6656   // 16B-aligned (6656*4 = 26624 bytes)

__global__ __launch_bounds__(256, 2)
void convcaps_k1(const float* __restrict__ x,    // [B,H,W,64] ch = d*8+c
                 const float* __restrict__ AW,   // [64 dc][64] dc*64 + n*8 + o
                 const float* __restrict__ CTW,  // [9][8 din][512] c*64+dh*8+n
                 const float* __restrict__ CTB)  // [512]
{
    extern __shared__ float sm[];
    float* s_u  = sm;             // 16640 (aliases s_in + s_w; written post-conv)
    float* s_in = sm;             // 6630 used (3 rows x 34 cols, stride 65)
    float* s_w  = sm + SW_OFF;    // 2 x 4096 double-buffered weight slabs (16B aligned)
    float* sA   = sm + 16640;     // 4096

    const int tid = threadIdx.x;  // 0..255
    const int b  = blockIdx.z;
    const int h  = blockIdx.y;
    const int w0 = blockIdx.x * 32;

    // ---- stage A matrix (read only in phase B) ----
    #pragma unroll
    for (int j = 0; j < 4; j++)
        ((float4*)sA)[tid + j * 256] = __ldg((const float4*)AW + tid + j * 256);

    // ---- load + transpose input tile: 3 rows x 34 cols x 64 ch ----
    for (int i = tid; i < 102 * 16; i += 256) {
        int q = i & 15;
        int p = i >> 4;                  // 0..101
        int row = p / 34, col = p % 34;
        int gh = h + row - 1, gw = w0 + col - 1;
        float4 val = make_float4(0.f, 0.f, 0.f, 0.f);
        if ((unsigned)gh < (unsigned)HH && (unsigned)gw < (unsigned)WW)
            val = *(const float4*)(x + (((size_t)(b * HH + gh) * WW + gw) * 64) + q * 4);
        float* base = s_in + p * 65;
        int ch = q * 4;                  // ch = d*8+c -> store at c*8+d
        base[((ch    ) & 7) * 8 + ((ch    ) >> 3)] = val.x;
        base[((ch + 1) & 7) * 8 + ((ch + 1) >> 3)] = val.y;
        base[((ch + 2) & 7) * 8 + ((ch + 2) >> 3)] = val.z;
        base[((ch + 3) & 7) * 8 + ((ch + 3) >> 3)] = val.w;
    }

    const int c  = tid >> 5;     // warp id = input type
    const int pc = tid & 31;     // lane = pixel column

    // ---- accumulators: [dh][n-pair j], init to bias ----
    ull acc2[8][4];
    {
        const float4* bp = (const float4*)(CTB + c * 64);
        #pragma unroll
        for (int dh = 0; dh < 8; dh++) {
            float4 b0 = __ldg(bp + dh * 2), b1 = __ldg(bp + dh * 2 + 1);
            PACK2(acc2[dh][0], b0.x, b0.y);
            PACK2(acc2[dh][1], b0.z, b0.w);
            PACK2(acc2[dh][2], b1.x, b1.y);
            PACK2(acc2[dh][3], b1.z, b1.w);
        }
    }

    // stage tap-0 weight slab: 4096 fl = 1024 float4, 4 per thread
    #pragma unroll
    for (int j = 0; j < 4; j++)
        ((float4*)s_w)[tid + j * 256] = __ldg((const float4*)CTW + tid + j * 256);
    __syncthreads();

    for (int tap = 0; tap < 9; tap++) {
        float4 wn[4];
        if (tap < 8) {
            #pragma unroll
            for (int j = 0; j < 4; j++)
                wn[j] = __ldg((const float4*)CTW + (tap + 1) * 1024 + tid + j * 256);
        }

        const float* wslab = s_w + (tap & 1) * 4096;
        const int ky = tap / 3, kx = tap % 3;
        const float* inb0 = s_in + (ky * 34 + pc + kx) * 65 + c * 8;

        #pragma unroll
        for (int din = 0; din < 8; din++) {
            float iv = inb0[din];
            ull iv2; PACK2(iv2, iv, iv);
            // weights for (c, all dh,n): 64 fl, broadcast across warp
            const ulonglong2* wq = (const ulonglong2*)(wslab + din * 512 + c * 64);
            #pragma unroll
            for (int dh = 0; dh < 8; dh++) {
                ulonglong2 wa = wq[dh * 2], wb = wq[dh * 2 + 1];
                FFMA2(acc2[dh][0], iv2, wa.x, acc2[dh][0]);
                FFMA2(acc2[dh][1], iv2, wa.y, acc2[dh][1]);
                FFMA2(acc2[dh][2], iv2, wb.x, acc2[dh][2]);
                FFMA2(acc2[dh][3], iv2, wb.y, acc2[dh][3]);
            }
        }

        if (tap < 8) {
            float* alt = s_w + ((tap + 1) & 1) * 4096;
            #pragma unroll
            for (int j = 0; j < 4; j++)
                ((float4*)alt)[tid + j * 256] = wn[j];
        }
        __syncthreads();
    }

    // ---- store u into s_u[px*520 + (dh*8+c)*8 + n]  (aliases s_in/s_w) ----
    #pragma unroll
    for (int dh = 0; dh < 8; dh++) {
        float r[8];
        #pragma unroll
        for (int j = 0; j < 4; j++)
            UNPACK2(r[2 * j], r[2 * j + 1], acc2[dh][j]);
        float* up = s_u + pc * SUP + (dh * 8 + c) * 8;
        *(float4*)(up)     = make_float4(r[0], r[1], r[2], r[3]);
        *(float4*)(up + 4) = make_float4(r[4], r[5], r[6], r[7]);
    }
    __syncthreads();

    // ================= Phase B: attention =================
    const int px = tid >> 3;     // 0..31
    const int n  = tid & 7;

    // u row for this (px, n): stride 520 -> conflict-light scalar reads
    float uv[64];
    {
        const float* up = s_u + px * SUP + n;
        #pragma unroll
        for (int dc = 0; dc < 64; dc++)
            uv[dc] = up[dc * 8];
    }

    float lg[8] = {0.f, 0.f, 0.f, 0.f, 0.f, 0.f, 0.f, 0.f};
    #pragma unroll 8
    for (int dc = 0; dc < 64; dc++) {
        const float4* ap = (const float4*)(sA + dc * 64 + n * 8);
        float4 a0 = ap[0], a1 = ap[1];
        float u0 = uv[dc];
        lg[0] = fmaf(u0, a0.x, lg[0]);
        lg[1] = fmaf(u0, a0.y, lg[1]);
        lg[2] = fmaf(u0, a0.z, lg[2]);
        lg[3] = fmaf(u0, a0.w, lg[3]);
        lg[4] = fmaf(u0, a1.x, lg[4]);
        lg[5] = fmaf(u0, a1.y, lg[5]);
        lg[6] = fmaf(u0, a1.z, lg[6]);
        lg[7] = fmaf(u0, a1.w, lg[7]);
    }

    float m = lg[0];
    #pragma unroll
    for (int o = 1; o < 8; o++) m = fmaxf(m, lg[o]);
    float att[8];
    float s = 0.f;
    #pragma unroll
    for (int o = 0; o < 8; o++) { att[o] = __expf(lg[o] - m); s += att[o]; }
    float inv = 1.f / s;
    #pragma unroll
    for (int o = 0; o < 8; o++) att[o] *= inv;

    float v[8];
    #pragma unroll
    for (int d = 0; d < 8; d++) {
        float acc = 0.f;
        #pragma unroll
        for (int o = 0; o < 8; o++)
            acc = fmaf(uv[d * 8 + o], att[o], acc);
        v[d] = acc;
    }

    size_t pix = ((size_t)(b * HH + h) * WW + w0 + px);
    float* vp = g_v + pix * 64 + n * 8;
    *(float4*)(vp)     = make_float4(v[0], v[1], v[2], v[3]);
    *(float4*)(vp + 4) = make_float4(v[4], v[5], v[6], v[7]);
}

// ---------------------------------------------------------------------------
// K2: FeaExt (grouped 3x3) + ReLU + CapsAct (grouped 1x1) -> out
// ---------------------------------------------------------------------------
#define SVP 66
#define K2_SMEM_FLOATS (204 * SVP + 4608 + 512 + 64 + 64)
#define K2_SMEM_BYTES  (K2_SMEM_FLOATS * 4)

__global__ __launch_bounds__(256, 3)
void convcaps_k2(const float* __restrict__ FW,
                 const float* __restrict__ FB,
                 const float* __restrict__ CW,
                 const float* __restrict__ CB,
                 float* __restrict__ out)
{
    extern __shared__ float sm2[];
    float* s_v  = sm2;                    // 204*66 = 13464
    float* s_fw = s_v + 204 * SVP;        // 4608   (13464*4 = 53856 B ≡ 0 mod 16)
    float* s_cw = s_fw + 4608;
    float* s_fb = s_cw + 512;
    float* s_cb = s_fb + 64;

    const int tid = threadIdx.x;
    const int pc  = tid & 31;
    const int n   = tid >> 5;

    const int b  = blockIdx.z;
    const int h0 = blockIdx.y * 4;
    const int w0 = blockIdx.x * 32;

    for (int i = tid; i < 204 * 32; i += 256) {
        int hp = i >> 5;
        int q  = i & 31;
        int row  = hp / 34;
        int colh = hp % 34;
        int gh = h0 + row - 1;
        int gw = w0 + colh - 1;
        float2 val = make_float2(0.f, 0.f);
        if ((unsigned)gh < (unsigned)HH && (unsigned)gw < (unsigned)WW)
            val = *(const float2*)(g_v + (((size_t)(b * HH + gh) * WW + gw) * 64) + q * 2);
        *(float2*)(s_v + hp * SVP + q * 2) = val;
    }
    for (int i = tid; i < 1152; i += 256) ((float4*)s_fw)[i] = __ldg((const float4*)FW + i);
    if (tid < 128) ((float4*)s_cw)[tid] = __ldg((const float4*)CW + tid);
    if (tid < 64) { s_fb[tid] = __ldg(FB + tid); s_cb[tid] = __ldg(CB + tid); }
    __syncthreads();

    ull h1[4][4];
    {
        const ulonglong2* fb = (const ulonglong2*)(s_fb + n * 8);
        ulonglong2 f0 = fb[0], f1 = fb[1];
        #pragma unroll
        for (int pr = 0; pr < 4; pr++) {
            h1[pr][0] = f0.x; h1[pr][1] = f0.y;
            h1[pr][2] = f1.x; h1[pr][3] = f1.y;
        }
    }

    #pragma unroll
    for (int tap = 0; tap < 9; tap++) {
        const int ky = tap / 3, kx = tap % 3;
        const float* vbase = s_v + (ky * 34 + pc + kx) * SVP + n * 8;
        #pragma unroll
        for (int d = 0; d < 8; d++) {
            const ulonglong2* wp = (const ulonglong2*)(s_fw + (tap * 8 + d) * 64 + n * 8);
            ulonglong2 wA = wp[0], wB = wp[1];
            const float* vp = vbase + d;
            #pragma unroll
            for (int pr = 0; pr < 4; pr++) {
                float iv = vp[pr * (34 * SVP)];
                ull iv2; PACK2(iv2, iv, iv);
                FFMA2(h1[pr][0], iv2, wA.x, h1[pr][0]);
                FFMA2(h1[pr][1], iv2, wA.y, h1[pr][1]);
                FFMA2(h1[pr][2], iv2, wB.x, h1[pr][2]);
                FFMA2(h1[pr][3], iv2, wB.y, h1[pr][3]);
            }
        }
    }

    const ulonglong2* cbp = (const ulonglong2*)(s_cb + n * 8);
    ulonglong2 cb0 = cbp[0], cb1 = cbp[1];

    #pragma unroll
    for (int pr = 0; pr < 4; pr++) {
        float e[8];
        #pragma unroll
        for (int j = 0; j < 4; j++)
            UNPACK2(e[2 * j], e[2 * j + 1], h1[pr][j]);
        #pragma unroll
        for (int k = 0; k < 8; k++) e[k] = fmaxf(e[k], 0.f);

        ull h2[4] = {cb0.x, cb0.y, cb1.x, cb1.y};
        #pragma unroll
        for (int k = 0; k < 8; k++) {
            ull he2; PACK2(he2, e[k], e[k]);
            const ulonglong2* cwp = (const ulonglong2*)(s_cw + k * 64 + n * 8);
            ulonglong2 cA = cwp[0], cB = cwp[1];
            FFMA2(h2[0], he2, cA.x, h2[0]);
            FFMA2(h2[1], he2, cA.y, h2[1]);
            FFMA2(h2[2], he2, cB.x, h2[2]);
            FFMA2(h2[3], he2, cB.y, h2[3]);
        }

        float r[8];
        #pragma unroll
        for (int j = 0; j < 4; j++)
            UNPACK2(r[2 * j], r[2 * j + 1], h2[j]);

        const int gh = h0 + pr, gw = w0 + pc;
        float* ob = out + ((size_t)(b * HH + gh) * WW + gw) * 64;
        #pragma unroll
        for (int f = 0; f < 8; f++)
            ob[f * 8 + n] = r[f];
    }
}

// ---------------------------------------------------------------------------
extern "C" void kernel_launch(void* const* d_in, const int* in_sizes, int n_in,
                              void* d_out, int out_size) {
    (void)in_sizes; (void)n_in; (void)out_size;
    const float* x   = (const float*)d_in[0];
    const float* AW  = (const float*)d_in[1];
    const float* CTW = (const float*)d_in[2];
    const float* CTB = (const float*)d_in[3];
    const float* FW  = (const float*)d_in[4];
    const float* FB  = (const float*)d_in[5];
    const float* CW  = (const float*)d_in[6];
    const float* CB  = (const float*)d_in[7];

    cudaFuncSetAttribute(convcaps_k1,
                         cudaFuncAttributeMaxDynamicSharedMemorySize, K1_SMEM_BYTES);
    cudaFuncSetAttribute(convcaps_k2,
                         cudaFuncAttributeMaxDynamicSharedMemorySize, K2_SMEM_BYTES);

    dim3 grid1(WW / 32, HH, BB);
    convcaps_k1<<<grid1, 256, K1_SMEM_BYTES>>>(x, AW, CTW, CTB);

    dim3 grid2(WW / 32, HH / 4, BB);
    convcaps_k2<<<grid2, 256, K2_SMEM_BYTES>>>(FW, FB, CW, CB, (float*)d_out);
}

// round 9
// speedup vs baseline: 1.4497x; 1.0859x over previous
#include <cuda_runtime.h>
#include <cuda_bf16.h>
#include <math.h>

#define BB 32
#define HH 64
#define WW 64

typedef unsigned long long ull;

#define FFMA2(d, a, b, c) \
    asm("fma.rn.f32x2 %0, %1, %2, %3;" : "=l"(d) : "l"(a), "l"(b), "l"(c))
#define PACK2(dst, lo, hi) \
    asm("mov.b64 %0, {%1, %2};" : "=l"(dst) : "f"(lo), "f"(hi))
#define UNPACK2(lo, hi, src) \
    asm("mov.b64 {%0, %1}, %2;" : "=f"(lo), "=f"(hi) : "l"(src))

// v scratch: [pix][n*8+d]  (32 MB)
__device__ float g_v[(size_t)BB * HH * WW * 64];

// ---------------------------------------------------------------------------
// K1: ConvTrans + attention fused; u lives in REGISTERS, reduced via smem atomics.
// Tile: 2 rows x 32 cols (64 px). 512 threads = 16 warps.
//   Conv: warp w -> (c = w>>1, half = w&1); lane = column pc.
//     Thread: 2 px (rows) x 32 outputs (dh in half, all n) = 32 packed f32x2 accs.
//     Weights (8 LDS.128/tap/din, warp-broadcast) double-buffered in smem.
//   Attention: partial logits per (c,half) thread -> atomicAdd into s_lg;
//     softmax by (px,n) threads; v reduced via atomicAdd into s_vs; write g_v.
// smem (floats):
//   s_in 4*34*65 = 8840 | s_w 2*4096 = 8192 | sA 4096 |
//   s_lg 64*66 = 4224   | s_vs 64*66 = 4224   -> total 29576 fl = 115.5 KB
// ---------------------------------------------------------------------------
#define SW_OFF   8840
#define SA_OFF   17032
#define LG_OFF   21128
#define VS_OFF   25352
#define K1_SMEM_FLOATS 29576
#define K1_SMEM_BYTES  (K1_SMEM_FLOATS * 4)
#define SLP 66

__global__ __launch_bounds__(512, 1)
void convcaps_k1(const float* __restrict__ x,    // [B,H,W,64] ch = d*8+c
                 const float* __restrict__ AW,   // [64 dc][64] dc*64 + n*8 + o
                 const float* __restrict__ CTW,  // [9][8 din][512] c*64+dh*8+n
                 const float* __restrict__ CTB)  // [512]
{
    extern __shared__ float sm[];
    float* s_in = sm;            // stride 65 per pixel, ch stored c*8+d
    float* s_w  = sm + SW_OFF;
    float* sA   = sm + SA_OFF;
    float* s_lg = sm + LG_OFF;   // [px][o*8+n], stride 66
    float* s_vs = sm + VS_OFF;   // [px][n*8+d], stride 66

    const int tid = threadIdx.x;   // 0..511
    const int b  = blockIdx.z;
    const int h0 = blockIdx.y * 2;
    const int w0 = blockIdx.x * 32;

    // ---- zero reduction buffers (8448 fl = 2112 float4) ----
    for (int i = tid; i < 2112; i += 512)
        ((float4*)s_lg)[i] = make_float4(0.f, 0.f, 0.f, 0.f);

    // ---- stage A matrix ----
    ((float4*)sA)[tid]       = __ldg((const float4*)AW + tid);
    ((float4*)sA)[tid + 512] = __ldg((const float4*)AW + tid + 512);

    // ---- load + transpose input tile: 4 rows x 34 cols x 64 ch ----
    for (int i = tid; i < 136 * 16; i += 512) {
        int q = i & 15;
        int p = i >> 4;                  // 0..135
        int row = p / 34, col = p % 34;
        int gh = h0 + row - 1, gw = w0 + col - 1;
        float4 val = make_float4(0.f, 0.f, 0.f, 0.f);
        if ((unsigned)gh < (unsigned)HH && (unsigned)gw < (unsigned)WW)
            val = *(const float4*)(x + (((size_t)(b * HH + gh) * WW + gw) * 64) + q * 4);
        float* base = s_in + p * 65;
        int ch = q * 4;                  // ch = d*8+c -> store at c*8+d
        base[((ch    ) & 7) * 8 + ((ch    ) >> 3)] = val.x;
        base[((ch + 1) & 7) * 8 + ((ch + 1) >> 3)] = val.y;
        base[((ch + 2) & 7) * 8 + ((ch + 2) >> 3)] = val.z;
        base[((ch + 3) & 7) * 8 + ((ch + 3) >> 3)] = val.w;
    }

    const int wid  = tid >> 5;
    const int c    = wid >> 1;     // input type
    const int half = wid & 1;      // dh half: dh = half*4 + dh'
    const int pc   = tid & 31;     // column

    // ---- accumulators [px=2][dh'=4][npair=4], init bias ----
    ull acc[2][4][4];
    {
        #pragma unroll
        for (int dq = 0; dq < 4; dq++) {
            const float4* bp = (const float4*)(CTB + c * 64 + (half * 4 + dq) * 8);
            float4 b0 = __ldg(bp), b1 = __ldg(bp + 1);
            ull p0, p1, p2, p3;
            PACK2(p0, b0.x, b0.y);
            PACK2(p1, b0.z, b0.w);
            PACK2(p2, b1.x, b1.y);
            PACK2(p3, b1.z, b1.w);
            #pragma unroll
            for (int px = 0; px < 2; px++) {
                acc[px][dq][0] = p0; acc[px][dq][1] = p1;
                acc[px][dq][2] = p2; acc[px][dq][3] = p3;
            }
        }
    }

    // stage tap-0 weight slab (4096 fl = 1024 float4; 2 per thread)
    ((float4*)s_w)[tid]       = __ldg((const float4*)CTW + tid);
    ((float4*)s_w)[tid + 512] = __ldg((const float4*)CTW + tid + 512);
    __syncthreads();

    for (int tap = 0; tap < 9; tap++) {
        float4 wn0, wn1;
        if (tap < 8) {
            wn0 = __ldg((const float4*)CTW + (tap + 1) * 1024 + tid);
            wn1 = __ldg((const float4*)CTW + (tap + 1) * 1024 + tid + 512);
        }

        const float* wslab = s_w + (tap & 1) * 4096;
        const int ky = tap / 3, kx = tap % 3;
        const float* iv0p = s_in + ((ky    ) * 34 + pc + kx) * 65 + c * 8;
        const float* iv1p = iv0p + 34 * 65;

        #pragma unroll
        for (int din = 0; din < 8; din++) {
            float iv0 = iv0p[din];
            float iv1 = iv1p[din];
            ull iva, ivb;
            PACK2(iva, iv0, iv0);
            PACK2(ivb, iv1, iv1);
            // weights for (c, half): 32 fl = 8 x LDS.128, warp-broadcast
            const ulonglong2* wq =
                (const ulonglong2*)(wslab + din * 512 + c * 64 + half * 32);
            #pragma unroll
            for (int dq = 0; dq < 4; dq++) {
                ulonglong2 wa = wq[dq * 2], wb = wq[dq * 2 + 1];
                FFMA2(acc[0][dq][0], iva, wa.x, acc[0][dq][0]);
                FFMA2(acc[0][dq][1], iva, wa.y, acc[0][dq][1]);
                FFMA2(acc[0][dq][2], iva, wb.x, acc[0][dq][2]);
                FFMA2(acc[0][dq][3], iva, wb.y, acc[0][dq][3]);
                FFMA2(acc[1][dq][0], ivb, wa.x, acc[1][dq][0]);
                FFMA2(acc[1][dq][1], ivb, wa.y, acc[1][dq][1]);
                FFMA2(acc[1][dq][2], ivb, wb.x, acc[1][dq][2]);
                FFMA2(acc[1][dq][3], ivb, wb.y, acc[1][dq][3]);
            }
        }

        if (tap < 8) {
            float* alt = s_w + ((tap + 1) & 1) * 4096;
            ((float4*)alt)[tid]       = wn0;
            ((float4*)alt)[tid + 512] = wn1;
        }
        __syncthreads();
    }

    // ---- unpack u into scalar regs: u[px][dh'][n] ----
    float u[2][4][8];
    #pragma unroll
    for (int px = 0; px < 2; px++)
        #pragma unroll
        for (int dq = 0; dq < 4; dq++)
            #pragma unroll
            for (int j = 0; j < 4; j++)
                UNPACK2(u[px][dq][2 * j], u[px][dq][2 * j + 1], acc[px][dq][j]);

    // ---- partial logits -> atomicAdd into s_lg[px][o*8+n] ----
    #pragma unroll
    for (int px = 0; px < 2; px++) {
        const int pxg = px * 32 + pc;
        #pragma unroll
        for (int n = 0; n < 8; n++) {
            #pragma unroll
            for (int oq = 0; oq < 2; oq++) {
                float4 a = make_float4(0.f, 0.f, 0.f, 0.f);
                #pragma unroll
                for (int dq = 0; dq < 4; dq++) {
                    const float4 av = *(const float4*)(sA +
                        ((half * 4 + dq) * 8 + c) * 64 + n * 8 + oq * 4);
                    float uu = u[px][dq][n];
                    a.x = fmaf(uu, av.x, a.x);
                    a.y = fmaf(uu, av.y, a.y);
                    a.z = fmaf(uu, av.z, a.z);
                    a.w = fmaf(uu, av.w, a.w);
                }
                float* lp = s_lg + pxg * SLP + n;
                atomicAdd(lp + (oq * 4 + 0) * 8, a.x);
                atomicAdd(lp + (oq * 4 + 1) * 8, a.y);
                atomicAdd(lp + (oq * 4 + 2) * 8, a.z);
                atomicAdd(lp + (oq * 4 + 3) * 8, a.w);
            }
        }
    }
    __syncthreads();

    // ---- softmax over o: thread = (px = tid>>3, n = tid&7); att in place ----
    {
        const int pxs = tid >> 3;
        const int ns  = tid & 7;
        float* lp = s_lg + pxs * SLP + ns;
        float l[8];
        float m = -1e30f;
        #pragma unroll
        for (int o = 0; o < 8; o++) { l[o] = lp[o * 8]; m = fmaxf(m, l[o]); }
        float s = 0.f;
        #pragma unroll
        for (int o = 0; o < 8; o++) { l[o] = __expf(l[o] - m); s += l[o]; }
        float inv = 1.f / s;
        #pragma unroll
        for (int o = 0; o < 8; o++) lp[o * 8] = l[o] * inv;
    }
    __syncthreads();

    // ---- v: atomicAdd u[px][dh][n]*att[c][n] into s_vs[px][n*8+dh] ----
    #pragma unroll
    for (int px = 0; px < 2; px++) {
        const int pxg = px * 32 + pc;
        #pragma unroll
        for (int n = 0; n < 8; n++) {
            float a = s_lg[pxg * SLP + c * 8 + n];   // att[o=c][n]
            float* vp = s_vs + pxg * SLP + n * 8 + half * 4;
            atomicAdd(vp + 0, u[px][0][n] * a);
            atomicAdd(vp + 1, u[px][1][n] * a);
            atomicAdd(vp + 2, u[px][2][n] * a);
            atomicAdd(vp + 3, u[px][3][n] * a);
        }
    }
    __syncthreads();

    // ---- write v: thread = (px, n) -> g_v[pix][n*8 + d(0..7)] ----
    {
        const int pxs = tid >> 3;
        const int ns  = tid & 7;
        const int r   = pxs >> 5, pcx = pxs & 31;
        const float* vp = s_vs + pxs * SLP + ns * 8;
        float4 v0 = make_float4(vp[0], vp[1], vp[2], vp[3]);
        float4 v1 = make_float4(vp[4], vp[5], vp[6], vp[7]);
        size_t pix = ((size_t)(b * HH + h0 + r) * WW + w0 + pcx);
        float* gp = g_v + pix * 64 + ns * 8;
        *(float4*)(gp)     = v0;
        *(float4*)(gp + 4) = v1;
    }
}

// ---------------------------------------------------------------------------
// K2: FeaExt (grouped 3x3) + ReLU + CapsAct (grouped 1x1) -> out  (unchanged)
// ---------------------------------------------------------------------------
#define SVP 66
#define K2_SMEM_FLOATS (204 * SVP + 4608 + 512 + 64 + 64)
#define K2_SMEM_BYTES  (K2_SMEM_FLOATS * 4)

__global__ __launch_bounds__(256, 3)
void convcaps_k2(const float* __restrict__ FW,
                 const float* __restrict__ FB,
                 const float* __restrict__ CW,
                 const float* __restrict__ CB,
                 float* __restrict__ out)
{
    extern __shared__ float sm2[];
    float* s_v  = sm2;
    float* s_fw = s_v + 204 * SVP;
    float* s_cw = s_fw + 4608;
    float* s_fb = s_cw + 512;
    float* s_cb = s_fb + 64;

    const int tid = threadIdx.x;
    const int pc  = tid & 31;
    const int n   = tid >> 5;

    const int b  = blockIdx.z;
    const int h0 = blockIdx.y * 4;
    const int w0 = blockIdx.x * 32;

    for (int i = tid; i < 204 * 32; i += 256) {
        int hp = i >> 5;
        int q  = i & 31;
        int row  = hp / 34;
        int colh = hp % 34;
        int gh = h0 + row - 1;
        int gw = w0 + colh - 1;
        float2 val = make_float2(0.f, 0.f);
        if ((unsigned)gh < (unsigned)HH && (unsigned)gw < (unsigned)WW)
            val = *(const float2*)(g_v + (((size_t)(b * HH + gh) * WW + gw) * 64) + q * 2);
        *(float2*)(s_v + hp * SVP + q * 2) = val;
    }
    for (int i = tid; i < 1152; i += 256) ((float4*)s_fw)[i] = __ldg((const float4*)FW + i);
    if (tid < 128) ((float4*)s_cw)[tid] = __ldg((const float4*)CW + tid);
    if (tid < 64) { s_fb[tid] = __ldg(FB + tid); s_cb[tid] = __ldg(CB + tid); }
    __syncthreads();

    ull h1[4][4];
    {
        const ulonglong2* fb = (const ulonglong2*)(s_fb + n * 8);
        ulonglong2 f0 = fb[0], f1 = fb[1];
        #pragma unroll
        for (int pr = 0; pr < 4; pr++) {
            h1[pr][0] = f0.x; h1[pr][1] = f0.y;
            h1[pr][2] = f1.x; h1[pr][3] = f1.y;
        }
    }

    #pragma unroll
    for (int tap = 0; tap < 9; tap++) {
        const int ky = tap / 3, kx = tap % 3;
        const float* vbase = s_v + (ky * 34 + pc + kx) * SVP + n * 8;
        #pragma unroll
        for (int d = 0; d < 8; d++) {
            const ulonglong2* wp = (const ulonglong2*)(s_fw + (tap * 8 + d) * 64 + n * 8);
            ulonglong2 wA = wp[0], wB = wp[1];
            const float* vp = vbase + d;
            #pragma unroll
            for (int pr = 0; pr < 4; pr++) {
                float iv = vp[pr * (34 * SVP)];
                ull iv2; PACK2(iv2, iv, iv);
                FFMA2(h1[pr][0], iv2, wA.x, h1[pr][0]);
                FFMA2(h1[pr][1], iv2, wA.y, h1[pr][1]);
                FFMA2(h1[pr][2], iv2, wB.x, h1[pr][2]);
                FFMA2(h1[pr][3], iv2, wB.y, h1[pr][3]);
            }
        }
    }

    const ulonglong2* cbp = (const ulonglong2*)(s_cb + n * 8);
    ulonglong2 cb0 = cbp[0], cb1 = cbp[1];

    #pragma unroll
    for (int pr = 0; pr < 4; pr++) {
        float e[8];
        #pragma unroll
        for (int j = 0; j < 4; j++)
            UNPACK2(e[2 * j], e[2 * j + 1], h1[pr][j]);
        #pragma unroll
        for (int k = 0; k < 8; k++) e[k] = fmaxf(e[k], 0.f);

        ull h2[4] = {cb0.x, cb0.y, cb1.x, cb1.y};
        #pragma unroll
        for (int k = 0; k < 8; k++) {
            ull he2; PACK2(he2, e[k], e[k]);
            const ulonglong2* cwp = (const ulonglong2*)(s_cw + k * 64 + n * 8);
            ulonglong2 cA = cwp[0], cB = cwp[1];
            FFMA2(h2[0], he2, cA.x, h2[0]);
            FFMA2(h2[1], he2, cA.y, h2[1]);
            FFMA2(h2[2], he2, cB.x, h2[2]);
            FFMA2(h2[3], he2, cB.y, h2[3]);
        }

        float r[8];
        #pragma unroll
        for (int j = 0; j < 4; j++)
            UNPACK2(r[2 * j], r[2 * j + 1], h2[j]);

        const int gh = h0 + pr, gw = w0 + pc;
        float* ob = out + ((size_t)(b * HH + gh) * WW + gw) * 64;
        #pragma unroll
        for (int f = 0; f < 8; f++)
            ob[f * 8 + n] = r[f];
    }
}

// ---------------------------------------------------------------------------
extern "C" void kernel_launch(void* const* d_in, const int* in_sizes, int n_in,
                              void* d_out, int out_size) {
    (void)in_sizes; (void)n_in; (void)out_size;
    const float* x   = (const float*)d_in[0];
    const float* AW  = (const float*)d_in[1];
    const float* CTW = (const float*)d_in[2];
    const float* CTB = (const float*)d_in[3];
    const float* FW  = (const float*)d_in[4];
    const float* FB  = (const float*)d_in[5];
    const float* CW  = (const float*)d_in[6];
    const float* CB  = (const float*)d_in[7];

    cudaFuncSetAttribute(convcaps_k1,
                         cudaFuncAttributeMaxDynamicSharedMemorySize, K1_SMEM_BYTES);
    cudaFuncSetAttribute(convcaps_k2,
                         cudaFuncAttributeMaxDynamicSharedMemorySize, K2_SMEM_BYTES);

    dim3 grid1(WW / 32, HH / 2, BB);
    convcaps_k1<<<grid1, 512, K1_SMEM_BYTES>>>(x, AW, CTW, CTB);

    dim3 grid2(WW / 32, HH / 4, BB);
    convcaps_k2<<<grid2, 256, K2_SMEM_BYTES>>>(FW, FB, CW, CB, (float*)d_out);
}

// round 10
// speedup vs baseline: 1.5462x; 1.0665x over previous
#include <cuda_runtime.h>
#include <cuda_bf16.h>
#include <math.h>

#define BB 32
#define HH 64
#define WW 64

typedef unsigned long long ull;

#define FFMA2(d, a, b, c) \
    asm("fma.rn.f32x2 %0, %1, %2, %3;" : "=l"(d) : "l"(a), "l"(b), "l"(c))
#define PACK2(dst, lo, hi) \
    asm("mov.b64 %0, {%1, %2};" : "=l"(dst) : "f"(lo), "f"(hi))
#define UNPACK2(lo, hi, src) \
    asm("mov.b64 {%0, %1}, %2;" : "=f"(lo), "=f"(hi) : "l"(src))

// v scratch: [pix][n*8+d]  (32 MB)
__device__ float g_v[(size_t)BB * HH * WW * 64];

// ---------------------------------------------------------------------------
// K1: ConvTrans + attention fused; u exchanged through smem (NO atomics).
// Tile: 2 rows x 32 cols (64 px). 512 threads = 16 warps.
//   Conv (as R9): warp w -> (c = w>>1, half = w&1); lane = column pc.
//     Thread: 2 px x 32 outputs (dh in half, all n) = 32 packed f32x2 accs.
//     Weights warp-broadcast from double-buffered smem slabs.
//   u store: s_u[px][(d*8+c)*8 + n], stride 516 (516/4 odd -> STS.128 at floor).
//   Attention (as R6, validated): thread = (px, n); uv[64] in regs; softmax;
//     v -> g_v. No reduction buffers, no atomics.
// smem (floats): s_in 8840 | s_w 8192 | sA 4096 | s_u 64*516=33024  -> 54152
// ---------------------------------------------------------------------------
#define SW_OFF   8840
#define SA_OFF   17032
#define SU_OFF   21128
#define K1_SMEM_FLOATS 54152
#define K1_SMEM_BYTES  (K1_SMEM_FLOATS * 4)
#define SUP 516

__global__ __launch_bounds__(512, 1)
void convcaps_k1(const float* __restrict__ x,    // [B,H,W,64] ch = d*8+c
                 const float* __restrict__ AW,   // [64 dc][64] dc*64 + n*8 + o
                 const float* __restrict__ CTW,  // [9][8 din][512] c*64+dh*8+n
                 const float* __restrict__ CTB)  // [512]
{
    extern __shared__ float sm[];
    float* s_in = sm;            // stride 65 per pixel, ch stored c*8+d
    float* s_w  = sm + SW_OFF;   // 2 x 4096 double-buffered weight slabs
    float* sA   = sm + SA_OFF;   // 4096
    float* s_u  = sm + SU_OFF;   // [64 px][512], stride 516

    const int tid = threadIdx.x;   // 0..511
    const int b  = blockIdx.z;
    const int h0 = blockIdx.y * 2;
    const int w0 = blockIdx.x * 32;

    // ---- stage A matrix ----
    ((float4*)sA)[tid]       = __ldg((const float4*)AW + tid);
    ((float4*)sA)[tid + 512] = __ldg((const float4*)AW + tid + 512);

    // ---- load + transpose input tile: 4 rows x 34 cols x 64 ch ----
    for (int i = tid; i < 136 * 16; i += 512) {
        int q = i & 15;
        int p = i >> 4;                  // 0..135
        int row = p / 34, col = p % 34;
        int gh = h0 + row - 1, gw = w0 + col - 1;
        float4 val = make_float4(0.f, 0.f, 0.f, 0.f);
        if ((unsigned)gh < (unsigned)HH && (unsigned)gw < (unsigned)WW)
            val = *(const float4*)(x + (((size_t)(b * HH + gh) * WW + gw) * 64) + q * 4);
        float* base = s_in + p * 65;
        int ch = q * 4;                  // ch = d*8+c -> store at c*8+d
        base[((ch    ) & 7) * 8 + ((ch    ) >> 3)] = val.x;
        base[((ch + 1) & 7) * 8 + ((ch + 1) >> 3)] = val.y;
        base[((ch + 2) & 7) * 8 + ((ch + 2) >> 3)] = val.z;
        base[((ch + 3) & 7) * 8 + ((ch + 3) >> 3)] = val.w;
    }

    const int wid  = tid >> 5;
    const int c    = wid >> 1;     // input type
    const int half = wid & 1;      // dh half: dh = half*4 + dh'
    const int pc   = tid & 31;     // column

    // ---- accumulators [px=2][dh'=4][npair=4], init bias ----
    ull acc[2][4][4];
    {
        #pragma unroll
        for (int dq = 0; dq < 4; dq++) {
            const float4* bp = (const float4*)(CTB + c * 64 + (half * 4 + dq) * 8);
            float4 b0 = __ldg(bp), b1 = __ldg(bp + 1);
            ull p0, p1, p2, p3;
            PACK2(p0, b0.x, b0.y);
            PACK2(p1, b0.z, b0.w);
            PACK2(p2, b1.x, b1.y);
            PACK2(p3, b1.z, b1.w);
            #pragma unroll
            for (int px = 0; px < 2; px++) {
                acc[px][dq][0] = p0; acc[px][dq][1] = p1;
                acc[px][dq][2] = p2; acc[px][dq][3] = p3;
            }
        }
    }

    // stage tap-0 weight slab (4096 fl = 1024 float4; 2 per thread)
    ((float4*)s_w)[tid]       = __ldg((const float4*)CTW + tid);
    ((float4*)s_w)[tid + 512] = __ldg((const float4*)CTW + tid + 512);
    __syncthreads();

    for (int tap = 0; tap < 9; tap++) {
        float4 wn0, wn1;
        if (tap < 8) {
            wn0 = __ldg((const float4*)CTW + (tap + 1) * 1024 + tid);
            wn1 = __ldg((const float4*)CTW + (tap + 1) * 1024 + tid + 512);
        }

        const float* wslab = s_w + (tap & 1) * 4096;
        const int ky = tap / 3, kx = tap % 3;
        const float* iv0p = s_in + (ky * 34 + pc + kx) * 65 + c * 8;
        const float* iv1p = iv0p + 34 * 65;

        #pragma unroll
        for (int din = 0; din < 8; din++) {
            float iv0 = iv0p[din];
            float iv1 = iv1p[din];
            ull iva, ivb;
            PACK2(iva, iv0, iv0);
            PACK2(ivb, iv1, iv1);
            // weights for (c, half): 32 fl = 8 x LDS.128, warp-broadcast
            const ulonglong2* wq =
                (const ulonglong2*)(wslab + din * 512 + c * 64 + half * 32);
            #pragma unroll
            for (int dq = 0; dq < 4; dq++) {
                ulonglong2 wa = wq[dq * 2], wb = wq[dq * 2 + 1];
                FFMA2(acc[0][dq][0], iva, wa.x, acc[0][dq][0]);
                FFMA2(acc[0][dq][1], iva, wa.y, acc[0][dq][1]);
                FFMA2(acc[0][dq][2], iva, wb.x, acc[0][dq][2]);
                FFMA2(acc[0][dq][3], iva, wb.y, acc[0][dq][3]);
                FFMA2(acc[1][dq][0], ivb, wa.x, acc[1][dq][0]);
                FFMA2(acc[1][dq][1], ivb, wa.y, acc[1][dq][1]);
                FFMA2(acc[1][dq][2], ivb, wb.x, acc[1][dq][2]);
                FFMA2(acc[1][dq][3], ivb, wb.y, acc[1][dq][3]);
            }
        }

        if (tap < 8) {
            float* alt = s_w + ((tap + 1) & 1) * 4096;
            ((float4*)alt)[tid]       = wn0;
            ((float4*)alt)[tid + 512] = wn1;
        }
        __syncthreads();
    }

    // ---- store u to s_u[px][(d*8+c)*8 + n] = [px][d*64 + c*8 + n] ----
    #pragma unroll
    for (int px = 0; px < 2; px++) {
        const int pxg = px * 32 + pc;
        #pragma unroll
        for (int dq = 0; dq < 4; dq++) {
            float r[8];
            #pragma unroll
            for (int j = 0; j < 4; j++)
                UNPACK2(r[2 * j], r[2 * j + 1], acc[px][dq][j]);
            float* up = s_u + pxg * SUP + (half * 4 + dq) * 64 + c * 8;
            *(float4*)(up)     = make_float4(r[0], r[1], r[2], r[3]);
            *(float4*)(up + 4) = make_float4(r[4], r[5], r[6], r[7]);
        }
    }
    __syncthreads();

    // ================= Attention (R6-validated, per-thread) =================
    const int pxs = tid >> 3;     // 0..63: row = pxs>>5, col = pxs&31
    const int ns  = tid & 7;

    // uv[dc] = u[d*8+c][n] for this (px, n); addr = pxs*516 + dc*8 + ns
    float uv[64];
    {
        const float* up = s_u + pxs * SUP + ns;
        #pragma unroll
        for (int dc = 0; dc < 64; dc++)
            uv[dc] = up[dc * 8];
    }

    float lg[8] = {0.f, 0.f, 0.f, 0.f, 0.f, 0.f, 0.f, 0.f};
    #pragma unroll 8
    for (int dc = 0; dc < 64; dc++) {
        const float4* ap = (const float4*)(sA + dc * 64 + ns * 8);
        float4 a0 = ap[0], a1 = ap[1];
        float u0 = uv[dc];
        lg[0] = fmaf(u0, a0.x, lg[0]);
        lg[1] = fmaf(u0, a0.y, lg[1]);
        lg[2] = fmaf(u0, a0.z, lg[2]);
        lg[3] = fmaf(u0, a0.w, lg[3]);
        lg[4] = fmaf(u0, a1.x, lg[4]);
        lg[5] = fmaf(u0, a1.y, lg[5]);
        lg[6] = fmaf(u0, a1.z, lg[6]);
        lg[7] = fmaf(u0, a1.w, lg[7]);
    }

    float m = lg[0];
    #pragma unroll
    for (int o = 1; o < 8; o++) m = fmaxf(m, lg[o]);
    float att[8];
    float s = 0.f;
    #pragma unroll
    for (int o = 0; o < 8; o++) { att[o] = __expf(lg[o] - m); s += att[o]; }
    float inv = 1.f / s;
    #pragma unroll
    for (int o = 0; o < 8; o++) att[o] *= inv;

    float v[8];
    #pragma unroll
    for (int d = 0; d < 8; d++) {
        float acc2 = 0.f;
        #pragma unroll
        for (int o = 0; o < 8; o++)
            acc2 = fmaf(uv[d * 8 + o], att[o], acc2);
        v[d] = acc2;
    }

    size_t pix = ((size_t)(b * HH + h0 + (pxs >> 5)) * WW + w0 + (pxs & 31));
    float* vp = g_v + pix * 64 + ns * 8;
    *(float4*)(vp)     = make_float4(v[0], v[1], v[2], v[3]);
    *(float4*)(vp + 4) = make_float4(v[4], v[5], v[6], v[7]);
}

// ---------------------------------------------------------------------------
// K2: FeaExt (grouped 3x3) + ReLU + CapsAct (grouped 1x1) -> out  (unchanged)
// ---------------------------------------------------------------------------
#define SVP 66
#define K2_SMEM_FLOATS (204 * SVP + 4608 + 512 + 64 + 64)
#define K2_SMEM_BYTES  (K2_SMEM_FLOATS * 4)

__global__ __launch_bounds__(256, 3)
void convcaps_k2(const float* __restrict__ FW,
                 const float* __restrict__ FB,
                 const float* __restrict__ CW,
                 const float* __restrict__ CB,
                 float* __restrict__ out)
{
    extern __shared__ float sm2[];
    float* s_v  = sm2;
    float* s_fw = s_v + 204 * SVP;
    float* s_cw = s_fw + 4608;
    float* s_fb = s_cw + 512;
    float* s_cb = s_fb + 64;

    const int tid = threadIdx.x;
    const int pc  = tid & 31;
    const int n   = tid >> 5;

    const int b  = blockIdx.z;
    const int h0 = blockIdx.y * 4;
    const int w0 = blockIdx.x * 32;

    for (int i = tid; i < 204 * 32; i += 256) {
        int hp = i >> 5;
        int q  = i & 31;
        int row  = hp / 34;
        int colh = hp % 34;
        int gh = h0 + row - 1;
        int gw = w0 + colh - 1;
        float2 val = make_float2(0.f, 0.f);
        if ((unsigned)gh < (unsigned)HH && (unsigned)gw < (unsigned)WW)
            val = *(const float2*)(g_v + (((size_t)(b * HH + gh) * WW + gw) * 64) + q * 2);
        *(float2*)(s_v + hp * SVP + q * 2) = val;
    }
    for (int i = tid; i < 1152; i += 256) ((float4*)s_fw)[i] = __ldg((const float4*)FW + i);
    if (tid < 128) ((float4*)s_cw)[tid] = __ldg((const float4*)CW + tid);
    if (tid < 64) { s_fb[tid] = __ldg(FB + tid); s_cb[tid] = __ldg(CB + tid); }
    __syncthreads();

    ull h1[4][4];
    {
        const ulonglong2* fb = (const ulonglong2*)(s_fb + n * 8);
        ulonglong2 f0 = fb[0], f1 = fb[1];
        #pragma unroll
        for (int pr = 0; pr < 4; pr++) {
            h1[pr][0] = f0.x; h1[pr][1] = f0.y;
            h1[pr][2] = f1.x; h1[pr][3] = f1.y;
        }
    }

    #pragma unroll
    for (int tap = 0; tap < 9; tap++) {
        const int ky = tap / 3, kx = tap % 3;
        const float* vbase = s_v + (ky * 34 + pc + kx) * SVP + n * 8;
        #pragma unroll
        for (int d = 0; d < 8; d++) {
            const ulonglong2* wp = (const ulonglong2*)(s_fw + (tap * 8 + d) * 64 + n * 8);
            ulonglong2 wA = wp[0], wB = wp[1];
            const float* vp = vbase + d;
            #pragma unroll
            for (int pr = 0; pr < 4; pr++) {
                float iv = vp[pr * (34 * SVP)];
                ull iv2; PACK2(iv2, iv, iv);
                FFMA2(h1[pr][0], iv2, wA.x, h1[pr][0]);
                FFMA2(h1[pr][1], iv2, wA.y, h1[pr][1]);
                FFMA2(h1[pr][2], iv2, wB.x, h1[pr][2]);
                FFMA2(h1[pr][3], iv2, wB.y, h1[pr][3]);
            }
        }
    }

    const ulonglong2* cbp = (const ulonglong2*)(s_cb + n * 8);
    ulonglong2 cb0 = cbp[0], cb1 = cbp[1];

    #pragma unroll
    for (int pr = 0; pr < 4; pr++) {
        float e[8];
        #pragma unroll
        for (int j = 0; j < 4; j++)
            UNPACK2(e[2 * j], e[2 * j + 1], h1[pr][j]);
        #pragma unroll
        for (int k = 0; k < 8; k++) e[k] = fmaxf(e[k], 0.f);

        ull h2[4] = {cb0.x, cb0.y, cb1.x, cb1.y};
        #pragma unroll
        for (int k = 0; k < 8; k++) {
            ull he2; PACK2(he2, e[k], e[k]);
            const ulonglong2* cwp = (const ulonglong2*)(s_cw + k * 64 + n * 8);
            ulonglong2 cA = cwp[0], cB = cwp[1];
            FFMA2(h2[0], he2, cA.x, h2[0]);
            FFMA2(h2[1], he2, cA.y, h2[1]);
            FFMA2(h2[2], he2, cB.x, h2[2]);
            FFMA2(h2[3], he2, cB.y, h2[3]);
        }

        float r[8];
        #pragma unroll
        for (int j = 0; j < 4; j++)
            UNPACK2(r[2 * j], r[2 * j + 1], h2[j]);

        const int gh = h0 + pr, gw = w0 + pc;
        float* ob = out + ((size_t)(b * HH + gh) * WW + gw) * 64;
        #pragma unroll
        for (int f = 0; f < 8; f++)
            ob[f * 8 + n] = r[f];
    }
}

// ---------------------------------------------------------------------------
extern "C" void kernel_launch(void* const* d_in, const int* in_sizes, int n_in,
                              void* d_out, int out_size) {
    (void)in_sizes; (void)n_in; (void)out_size;
    const float* x   = (const float*)d_in[0];
    const float* AW  = (const float*)d_in[1];
    const float* CTW = (const float*)d_in[2];
    const float* CTB = (const float*)d_in[3];
    const float* FW  = (const float*)d_in[4];
    const float* FB  = (const float*)d_in[5];
    const float* CW  = (const float*)d_in[6];
    const float* CB  = (const float*)d_in[7];

    cudaFuncSetAttribute(convcaps_k1,
                         cudaFuncAttributeMaxDynamicSharedMemorySize, K1_SMEM_BYTES);
    cudaFuncSetAttribute(convcaps_k2,
                         cudaFuncAttributeMaxDynamicSharedMemorySize, K2_SMEM_BYTES);

    dim3 grid1(WW / 32, HH / 2, BB);
    convcaps_k1<<<grid1, 512, K1_SMEM_BYTES>>>(x, AW, CTW, CTB);

    dim3 grid2(WW / 32, HH / 4, BB);
    convcaps_k2<<<grid2, 256, K2_SMEM_BYTES>>>(FW, FB, CW, CB, (float*)d_out);
}